// round 6
// baseline (speedup 1.0000x reference)
#include <cuda_runtime.h>
#include <cuda_bf16.h>
#include <cstdint>

// Problem constants
#define BB   8
#define NN   4096
#define MM   1024
#define CIN  32
#define KNB  64
#define NEGV (-1e10f)
#define R2F  (0.04f)

// Scratch (device globals: allocation-free)
__device__ int   g_fps[BB * MM];                 // FPS indices (within-batch)
__device__ float g_t[(size_t)BB * NN * 64];      // x @ W1[:32,:]  (8 MB)
__device__ int   g_nbr[(size_t)BB * MM * KNB];   // neighbor idx within batch, -1 invalid

// ---------------- helpers: packed f32x2 ----------------
__device__ __forceinline__ unsigned long long pack2(float lo, float hi) {
    unsigned long long r;
    asm("mov.b64 %0, {%1, %2};" : "=l"(r) : "f"(lo), "f"(hi));
    return r;
}
__device__ __forceinline__ unsigned long long bc2(float v) {
    unsigned long long r;
    asm("mov.b64 %0, {%1, %1};" : "=l"(r) : "f"(v));
    return r;
}
__device__ __forceinline__ void unpack2(unsigned long long v, float& lo, float& hi) {
    asm("mov.b64 {%0, %1}, %2;" : "=f"(lo), "=f"(hi) : "l"(v));
}
__device__ __forceinline__ void fma2(unsigned long long& acc, unsigned long long a, unsigned long long b) {
    asm("fma.rn.f32x2 %0, %1, %2, %0;" : "+l"(acc) : "l"(a), "l"(b));
}

__device__ __forceinline__ float sqdist(float ax, float ay, float az,
                                        float bx, float by, float bz) {
    float dx = ax - bx, dy = ay - by, dz = az - bz;
    // forced non-FMA left-assoc sum to best match XLA rounding
    return __fadd_rn(__fadd_rn(__fmul_rn(dx, dx), __fmul_rn(dy, dy)), __fmul_rn(dz, dz));
}

// ---------------- Kernel A: farthest point sampling ----------------
// one block per batch, 512 threads, 8 points/thread, dmin in registers
__global__ void fps_kernel(const float* __restrict__ pos) {
    extern __shared__ float sm[];
    float* sx = sm;
    float* sy = sm + NN;
    float* sz = sm + 2 * NN;
    __shared__ float rv[16];
    __shared__ int   ri[16];
    __shared__ int   slast;

    const int b = blockIdx.x;
    const int tid = threadIdx.x;
    const float* pb = pos + (size_t)b * NN * 3;

    for (int i = tid; i < NN; i += 512) {
        sx[i] = pb[i * 3 + 0];
        sy[i] = pb[i * 3 + 1];
        sz[i] = pb[i * 3 + 2];
    }
    float dmin[8];
#pragma unroll
    for (int j = 0; j < 8; ++j) dmin[j] = 1e10f;
    if (tid == 0) { g_fps[b * MM] = 0; slast = 0; }
    __syncthreads();

    int last = 0;
    const int base = tid * 8;
    for (int it = 1; it < MM; ++it) {
        float lx = sx[last], ly = sy[last], lz = sz[last];
        float bv = -1.0f; int bi = 0;
#pragma unroll
        for (int j = 0; j < 8; ++j) {
            int p = base + j;
            float d = sqdist(sx[p], sy[p], sz[p], lx, ly, lz);
            float dm = fminf(dmin[j], d);
            dmin[j] = dm;
            if (dm > bv) { bv = dm; bi = p; }   // strict > keeps lowest index
        }
#pragma unroll
        for (int off = 16; off; off >>= 1) {
            float ov = __shfl_down_sync(0xffffffffu, bv, off);
            int   oi = __shfl_down_sync(0xffffffffu, bi, off);
            if (ov > bv || (ov == bv && oi < bi)) { bv = ov; bi = oi; }
        }
        int w = tid >> 5;
        if ((tid & 31) == 0) { rv[w] = bv; ri[w] = bi; }
        __syncthreads();
        if (tid < 32) {
            float v2 = (tid < 16) ? rv[tid] : -2.0f;
            int   i2 = (tid < 16) ? ri[tid] : NN;
#pragma unroll
            for (int off = 8; off; off >>= 1) {
                float ov = __shfl_down_sync(0xffffffffu, v2, off);
                int   oi = __shfl_down_sync(0xffffffffu, i2, off);
                if (ov > v2 || (ov == v2 && oi < i2)) { v2 = ov; i2 = oi; }
            }
            if (tid == 0) { g_fps[b * MM + it] = i2; slast = i2; }
        }
        __syncthreads();
        last = slast;
    }
}

// ---------------- Kernel B: ball query + exact 64-NN selection ----------------
// grid (8 chunks, 8 batches), 256 threads (8 warps), warp per centroid
#define BCAP 512
__global__ void ballq_kernel(const float* __restrict__ pos) {
    extern __shared__ float sm[];
    float* sx = sm;
    float* sy = sm + NN;
    float* sz = sm + 2 * NN;
    unsigned long long* bufAll = (unsigned long long*)(sm + 3 * NN);

    const int b = blockIdx.y;
    const int chunk = blockIdx.x;
    const int tid = threadIdx.x;
    const int warpId = tid >> 5;
    const int lane = tid & 31;
    const float* pb = pos + (size_t)b * NN * 3;

    for (int i = tid; i < NN; i += 256) {
        sx[i] = pb[i * 3 + 0];
        sy[i] = pb[i * 3 + 1];
        sz[i] = pb[i * 3 + 2];
    }
    __syncthreads();

    unsigned long long* buf = bufAll + (size_t)warpId * BCAP;

    for (int c = chunk * 128 + warpId; c < chunk * 128 + 128; c += 8) {
        int gi = g_fps[b * MM + c];
        float cx = sx[gi], cy = sy[gi], cz = sz[gi];
        int cnt = 0;
        for (int basej = 0; basej < NN; basej += 32) {
            int j = basej + lane;
            float d2 = sqdist(sx[j], sy[j], sz[j], cx, cy, cz);
            bool in = (d2 <= R2F);
            unsigned m = __ballot_sync(0xffffffffu, in);
            if (in) {
                int off = cnt + __popc(m & ((1u << lane) - 1u));
                if (off < BCAP)
                    buf[off] = (((unsigned long long)__float_as_uint(d2)) << 32) | (unsigned)j;
            }
            cnt += __popc(m);
        }
        int cc = min(cnt, BCAP);
        __syncwarp();
        if (cc > KNB) {
            int n = KNB;
            while (n < cc) n <<= 1;            // n <= 512
            for (int i = cc + lane; i < n; i += 32) buf[i] = 0xffffffffffffffffull;
            __syncwarp();
            for (int k2 = 2; k2 <= n; k2 <<= 1) {
                for (int j2 = k2 >> 1; j2 > 0; j2 >>= 1) {
                    for (int i = lane; i < n; i += 32) {
                        int ixj = i ^ j2;
                        if (ixj > i) {
                            unsigned long long a = buf[i], q = buf[ixj];
                            bool up = ((i & k2) == 0);
                            if ((a > q) == up) { buf[i] = q; buf[ixj] = a; }
                        }
                    }
                    __syncwarp();
                }
            }
        }
        int nv = min(cc, KNB);
        for (int s = lane; s < KNB; s += 32) {
            int outi = (s < nv) ? (int)(buf[s] & 0xffffffffull) : -1;
            g_nbr[((size_t)(b * MM + c)) * KNB + s] = outi;
        }
        __syncwarp();
    }
}

// ---------------- Kernel C: t = x @ W1[0:32,:] (no bias) ----------------
__global__ void feat_kernel(const float* __restrict__ x, const float* __restrict__ W1) {
    __shared__ float Ws[CIN * 64];
    const int tid = threadIdx.x;
    for (int i = tid; i < CIN * 64; i += 256) Ws[i] = W1[i];
    __syncthreads();

    int g = blockIdx.x * 256 + tid;           // 131072 threads
    int p = g >> 2;
    int q = g & 3;

    float xr[32];
    const float4* xp = reinterpret_cast<const float4*>(x + (size_t)p * CIN);
#pragma unroll
    for (int k = 0; k < 8; ++k) {
        float4 v = xp[k];
        xr[4 * k + 0] = v.x; xr[4 * k + 1] = v.y; xr[4 * k + 2] = v.z; xr[4 * k + 3] = v.w;
    }
    float acc[16];
#pragma unroll
    for (int o = 0; o < 16; ++o) acc[o] = 0.0f;
#pragma unroll
    for (int i = 0; i < 32; ++i) {
        float xv = xr[i];
        const float4* wrow = reinterpret_cast<const float4*>(Ws + i * 64 + q * 16);
#pragma unroll
        for (int o4 = 0; o4 < 4; ++o4) {
            float4 w = wrow[o4];
            acc[o4 * 4 + 0] += xv * w.x;
            acc[o4 * 4 + 1] += xv * w.y;
            acc[o4 * 4 + 2] += xv * w.z;
            acc[o4 * 4 + 3] += xv * w.w;
        }
    }
    float4* tp = reinterpret_cast<float4*>(g_t + (size_t)p * 64 + q * 16);
#pragma unroll
    for (int o4 = 0; o4 < 4; ++o4)
        tp[o4] = make_float4(acc[o4 * 4 + 0], acc[o4 * 4 + 1], acc[o4 * 4 + 2], acc[o4 * 4 + 3]);
}

// ---------------- Kernel D: fused MLP + masked max-aggregate ----------------
// 256 threads = 4 groups of 64; group = centroid; thread = neighbor slot
// smem float layout:
//   W2S @0 (4096) | W3S @4096 (8192) | W1PS @12288 (192) | B1S @12480 (64)
//   B2S @12544 (64) | B3S @12608 (128) | RED @12736 (1024)  -> 13760 floats
#define SM_W3   4096
#define SM_W1P  12288
#define SM_B1   12480
#define SM_B2   12544
#define SM_B3   12608
#define SM_RED  12736
#define SM_TOT  13760

__global__ void __launch_bounds__(256) conv_kernel(
    const float* __restrict__ pos,
    const float* __restrict__ W1, const float* __restrict__ b1,
    const float* __restrict__ W2, const float* __restrict__ b2,
    const float* __restrict__ W3, const float* __restrict__ b3,
    float* __restrict__ out, int out_size)
{
    extern __shared__ float sm[];
    const int tid = threadIdx.x;

    for (int i = tid; i < 4096; i += 256) sm[i] = W2[i];
    for (int i = tid; i < 8192; i += 256) sm[SM_W3 + i] = W3[i];
    if (tid < 192) sm[SM_W1P + tid] = W1[CIN * 64 + tid];
    if (tid < 64)  sm[SM_B1 + tid] = b1[tid];
    if (tid < 64)  sm[SM_B2 + tid] = b2[tid];
    if (tid < 128) sm[SM_B3 + tid] = b3[tid];
    __syncthreads();

    const int group = tid >> 6;
    const int gtid = tid & 63;
    const int lane = tid & 31;
    const int wgrp = (tid >> 5) & 1;
    const int cid = blockIdx.x * 4 + group;   // 0..8191
    const int b = cid >> 10;

    const int gi = g_fps[cid];
    const float* pb = pos + (size_t)b * NN * 3;
    const float cx = pb[gi * 3 + 0], cy = pb[gi * 3 + 1], cz = pb[gi * 3 + 2];

    const int nj = g_nbr[(size_t)cid * KNB + gtid];
    const bool valid = (nj >= 0);
    const int jj = valid ? nj : gi;
    const float rx = pb[jj * 3 + 0] - cx;
    const float ry = pb[jj * 3 + 1] - cy;
    const float rz = pb[jj * 3 + 2] - cz;

    // ---- layer 1: h = relu(t + b1 + rel @ W1p) ----
    float h[64];
    const float4* tp = reinterpret_cast<const float4*>(g_t + ((size_t)b * NN + jj) * 64);
#pragma unroll
    for (int o4 = 0; o4 < 16; ++o4) {
        float4 tv = tp[o4];
        float4 bb = reinterpret_cast<const float4*>(sm + SM_B1)[o4];
        float4 w0 = reinterpret_cast<const float4*>(sm + SM_W1P)[o4];
        float4 w1 = reinterpret_cast<const float4*>(sm + SM_W1P + 64)[o4];
        float4 w2r = reinterpret_cast<const float4*>(sm + SM_W1P + 128)[o4];
        h[4 * o4 + 0] = fmaxf(tv.x + bb.x + rx * w0.x + ry * w1.x + rz * w2r.x, 0.0f);
        h[4 * o4 + 1] = fmaxf(tv.y + bb.y + rx * w0.y + ry * w1.y + rz * w2r.y, 0.0f);
        h[4 * o4 + 2] = fmaxf(tv.z + bb.z + rx * w0.z + ry * w1.z + rz * w2r.z, 0.0f);
        h[4 * o4 + 3] = fmaxf(tv.w + bb.w + rx * w0.w + ry * w1.w + rz * w2r.w, 0.0f);
    }

    // ---- layer 2: h2 = relu(h @ W2 + b2), f32x2 packed ----
    {
        unsigned long long acc2[32];
#pragma unroll
        for (int q = 0; q < 32; ++q)
            acc2[q] = pack2(sm[SM_B2 + 2 * q], sm[SM_B2 + 2 * q + 1]);
#pragma unroll
        for (int i = 0; i < 64; ++i) {
            unsigned long long hv = bc2(h[i]);
            const ulonglong2* wr = reinterpret_cast<const ulonglong2*>(sm + i * 64);
#pragma unroll
            for (int q = 0; q < 16; ++q) {
                ulonglong2 w = wr[q];
                fma2(acc2[2 * q + 0], hv, w.x);
                fma2(acc2[2 * q + 1], hv, w.y);
            }
        }
#pragma unroll
        for (int q = 0; q < 32; ++q) {
            float lo, hi;
            unpack2(acc2[q], lo, hi);
            h[2 * q + 0] = fmaxf(lo, 0.0f);
            h[2 * q + 1] = fmaxf(hi, 0.0f);
        }
    }

    // ---- layer 3 (4 tiles of 32 out) + masked max reduce ----
    for (int tile = 0; tile < 4; ++tile) {
        unsigned long long a3[16];
#pragma unroll
        for (int q = 0; q < 16; ++q)
            a3[q] = pack2(sm[SM_B3 + tile * 32 + 2 * q], sm[SM_B3 + tile * 32 + 2 * q + 1]);
#pragma unroll
        for (int i = 0; i < 64; ++i) {
            unsigned long long hv = bc2(h[i]);
            const ulonglong2* wr = reinterpret_cast<const ulonglong2*>(sm + SM_W3 + i * 128 + tile * 32);
#pragma unroll
            for (int q = 0; q < 8; ++q) {
                ulonglong2 w = wr[q];
                fma2(a3[2 * q + 0], hv, w.x);
                fma2(a3[2 * q + 1], hv, w.y);
            }
        }
        float v[32];
#pragma unroll
        for (int q = 0; q < 16; ++q) {
            float lo, hi;
            unpack2(a3[q], lo, hi);
            v[2 * q + 0] = valid ? lo : NEGV;
            v[2 * q + 1] = valid ? hi : NEGV;
        }
#pragma unroll
        for (int s = 16; s; s >>= 1) {
#pragma unroll
            for (int c = 0; c < 32; ++c)
                v[c] = fmaxf(v[c], __shfl_xor_sync(0xffffffffu, v[c], s));
        }
        float* red = sm + SM_RED + ((group * 4 + tile) * 2 + wgrp) * 32;
        if (lane == 0) {
#pragma unroll
            for (int q = 0; q < 8; ++q)
                reinterpret_cast<float4*>(red)[q] =
                    make_float4(v[4 * q + 0], v[4 * q + 1], v[4 * q + 2], v[4 * q + 3]);
        }
        __syncthreads();
        if (wgrp == 0) {
            const float* redA = sm + SM_RED + ((group * 4 + tile) * 2) * 32;
            float a = redA[lane];
            float bq = redA[32 + lane];
            int off = cid * 128 + tile * 32 + lane;
            if (off < out_size) out[off] = fmaxf(a, bq);
        }
    }
}

// ---------------- Kernel E: pos_out + batch_out tails ----------------
__global__ void tail_kernel(const float* __restrict__ pos, float* __restrict__ out, int out_size) {
    int i = blockIdx.x * 256 + threadIdx.x;
    if (i >= BB * MM) return;
    int b = i >> 10;
    int gi = g_fps[i];
    const float* pb = pos + (size_t)b * NN * 3;
    const int OX = BB * MM * 128;              // 1048576
    const int OP = OX + BB * MM * 3;           // 1073152
    const int OT = OP + BB * MM;               // 1081344
    if (out_size >= OP) {
        out[OX + i * 3 + 0] = pb[gi * 3 + 0];
        out[OX + i * 3 + 1] = pb[gi * 3 + 1];
        out[OX + i * 3 + 2] = pb[gi * 3 + 2];
    }
    if (out_size >= OT) out[OP + i] = (float)b;
}

extern "C" void kernel_launch(void* const* d_in, const int* in_sizes, int n_in,
                              void* d_out, int out_size) {
    const float* x   = (const float*)d_in[0];
    const float* pos = (const float*)d_in[1];
    // d_in[2] = batch (implied by layout, unused)
    const float* W1  = (const float*)d_in[3];
    const float* b1  = (const float*)d_in[4];
    const float* W2  = (const float*)d_in[5];
    const float* b2  = (const float*)d_in[6];
    const float* W3  = (const float*)d_in[7];
    const float* b3  = (const float*)d_in[8];
    float* out = (float*)d_out;

    const int smA = 3 * NN * 4;                        // 49152
    const int smB = 3 * NN * 4 + 8 * BCAP * 8;         // 81920
    const int smD = SM_TOT * 4;                        // 55040

    cudaFuncSetAttribute(fps_kernel,   cudaFuncAttributeMaxDynamicSharedMemorySize, smA);
    cudaFuncSetAttribute(ballq_kernel, cudaFuncAttributeMaxDynamicSharedMemorySize, smB);
    cudaFuncSetAttribute(conv_kernel,  cudaFuncAttributeMaxDynamicSharedMemorySize, smD);

    fps_kernel<<<BB, 512, smA>>>(pos);
    ballq_kernel<<<dim3(8, BB), 256, smB>>>(pos);
    feat_kernel<<<(BB * NN * 4) / 256, 256>>>(x, W1);
    conv_kernel<<<(BB * MM) / 4, 256, smD>>>(pos, W1, b1, W2, b2, W3, b3, out, out_size);
    tail_kernel<<<(BB * MM) / 256, 256>>>(pos, out, out_size);
}

// round 7
// speedup vs baseline: 1.3283x; 1.3283x over previous
#include <cuda_runtime.h>
#include <cuda_bf16.h>
#include <cstdint>

// Problem constants
#define BB   8
#define NN   4096
#define MM   1024
#define CIN  32
#define KNB  64
#define NEGV (-1e10f)
#define R2F  (0.04f)

// Scratch (device globals: allocation-free)
__device__ int   g_fps[BB * MM];                 // FPS indices (within-batch)
__device__ float g_t[(size_t)BB * NN * 64];      // x @ W1[:32,:]  (8 MB)
__device__ int   g_nbr[(size_t)BB * MM * KNB];   // neighbor idx within batch, -1 invalid

typedef unsigned long long ull;

// ---------------- helpers: packed f32x2 ----------------
__device__ __forceinline__ ull pack2(float lo, float hi) {
    ull r; asm("mov.b64 %0, {%1, %2};" : "=l"(r) : "f"(lo), "f"(hi)); return r;
}
__device__ __forceinline__ ull bc2(float v) {
    ull r; asm("mov.b64 %0, {%1, %1};" : "=l"(r) : "f"(v)); return r;
}
__device__ __forceinline__ void unpack2(ull v, float& lo, float& hi) {
    asm("mov.b64 {%0, %1}, %2;" : "=f"(lo), "=f"(hi) : "l"(v));
}
__device__ __forceinline__ void fma2(ull& acc, ull a, ull b) {
    asm("fma.rn.f32x2 %0, %1, %2, %0;" : "+l"(acc) : "l"(a), "l"(b));
}
__device__ __forceinline__ ull add2(ull a, ull b) {
    ull r; asm("add.rn.f32x2 %0, %1, %2;" : "=l"(r) : "l"(a), "l"(b)); return r;
}
__device__ __forceinline__ ull mul2(ull a, ull b) {
    ull r; asm("mul.rn.f32x2 %0, %1, %2;" : "=l"(r) : "l"(a), "l"(b)); return r;
}
// packed sqdist of 2 points vs broadcast negated center: per-component identical
// to __fadd_rn(__fadd_rn(__fmul_rn(dx,dx),__fmul_rn(dy,dy)),__fmul_rn(dz,dz))
__device__ __forceinline__ ull sqdist2(ull X, ull Y, ull Z, ull ncx, ull ncy, ull ncz) {
    ull dx = add2(X, ncx), dy = add2(Y, ncy), dz = add2(Z, ncz);
    return add2(add2(mul2(dx, dx), mul2(dy, dy)), mul2(dz, dz));
}

__device__ __forceinline__ float sqdist(float ax, float ay, float az,
                                        float bx, float by, float bz) {
    float dx = ax - bx, dy = ay - by, dz = az - bz;
    return __fadd_rn(__fadd_rn(__fmul_rn(dx, dx), __fmul_rn(dy, dy)), __fmul_rn(dz, dz));
}

// ---------------- Kernel A: farthest point sampling ----------------
// one block per batch, 512 threads, 8 points/thread, coords + dmin in REGISTERS
__global__ void fps_kernel(const float* __restrict__ pos) {
    extern __shared__ float sm[];
    float* sx = sm;
    float* sy = sm + NN;
    float* sz = sm + 2 * NN;
    __shared__ float rv[16];
    __shared__ int   ri[16];
    __shared__ int   slast;

    const int b = blockIdx.x;
    const int tid = threadIdx.x;
    const float* pb = pos + (size_t)b * NN * 3;

    for (int i = tid; i < NN; i += 512) {
        sx[i] = pb[i * 3 + 0];
        sy[i] = pb[i * 3 + 1];
        sz[i] = pb[i * 3 + 2];
    }
    if (tid == 0) { g_fps[b * MM] = 0; slast = 0; }
    __syncthreads();

    // register-resident coords (packed pairs) + dmin
    const int base = tid * 8;
    ull X[4], Y[4], Z[4];
#pragma unroll
    for (int j = 0; j < 4; ++j) {
        X[j] = pack2(sx[base + 2 * j], sx[base + 2 * j + 1]);
        Y[j] = pack2(sy[base + 2 * j], sy[base + 2 * j + 1]);
        Z[j] = pack2(sz[base + 2 * j], sz[base + 2 * j + 1]);
    }
    float dmin[8];
#pragma unroll
    for (int j = 0; j < 8; ++j) dmin[j] = 1e10f;

    int last = 0;
    for (int it = 1; it < MM; ++it) {
        float lx = sx[last], ly = sy[last], lz = sz[last];
        ull nlx = bc2(-lx), nly = bc2(-ly), nlz = bc2(-lz);
        float bv = -1.0f; int bi = 0;
#pragma unroll
        for (int j = 0; j < 4; ++j) {
            ull s = sqdist2(X[j], Y[j], Z[j], nlx, nly, nlz);
            float d0, d1; unpack2(s, d0, d1);
            float m0 = fminf(dmin[2 * j + 0], d0); dmin[2 * j + 0] = m0;
            float m1 = fminf(dmin[2 * j + 1], d1); dmin[2 * j + 1] = m1;
            if (m0 > bv) { bv = m0; bi = base + 2 * j; }      // strict > keeps lowest idx
            if (m1 > bv) { bv = m1; bi = base + 2 * j + 1; }
        }
#pragma unroll
        for (int off = 16; off; off >>= 1) {
            float ov = __shfl_down_sync(0xffffffffu, bv, off);
            int   oi = __shfl_down_sync(0xffffffffu, bi, off);
            if (ov > bv || (ov == bv && oi < bi)) { bv = ov; bi = oi; }
        }
        int w = tid >> 5;
        if ((tid & 31) == 0) { rv[w] = bv; ri[w] = bi; }
        __syncthreads();
        if (tid < 32) {
            float v2 = (tid < 16) ? rv[tid] : -2.0f;
            int   i2 = (tid < 16) ? ri[tid] : NN;
#pragma unroll
            for (int off = 8; off; off >>= 1) {
                float ov = __shfl_down_sync(0xffffffffu, v2, off);
                int   oi = __shfl_down_sync(0xffffffffu, i2, off);
                if (ov > v2 || (ov == v2 && oi < i2)) { v2 = ov; i2 = oi; }
            }
            if (tid == 0) { g_fps[b * MM + it] = i2; slast = i2; }
        }
        __syncthreads();
        last = slast;
    }
}

// ---------------- Kernel B: ball query + exact 64-NN selection ----------------
// grid (64 chunks, 8 batches), 256 threads (8 warps), warp handles 2 centroids
#define BCAP 512
__global__ void ballq_kernel(const float* __restrict__ pos) {
    extern __shared__ float sm[];
    // packed coords: component c of points (i, i+2048) as float2 at [i]
    float2* spx = (float2*)sm;                 // 2048
    float2* spy = spx + 2048;
    float2* spz = spy + 2048;
    ull* bufAll = (ull*)(spz + 2048);          // 8 warps * 512

    const int b = blockIdx.y;
    const int chunk = blockIdx.x;              // 0..63
    const int tid = threadIdx.x;
    const int warpId = tid >> 5;
    const int lane = tid & 31;
    const unsigned lanelt = (1u << lane) - 1u;
    const float* pb = pos + (size_t)b * NN * 3;

    // coalesced fill of packed arrays
    for (int k = tid; k < NN * 3; k += 256) {
        float f = pb[k];
        int i = k / 3, comp = k - 3 * i;
        float* dst = (comp == 0) ? (float*)spx : (comp == 1) ? (float*)spy : (float*)spz;
        dst[(i & 2047) * 2 + (i >> 11)] = f;
    }
    __syncthreads();

    const ull* px = (const ull*)spx;
    const ull* py = (const ull*)spy;
    const ull* pz = (const ull*)spz;
    ull* buf = bufAll + (size_t)warpId * BCAP;

    for (int cc = 0; cc < 2; ++cc) {
        const int c = chunk * 16 + warpId * 2 + cc;
        const int gi = g_fps[b * MM + c];
        const int hi = gi >> 11, ii = gi & 2047;
        float2 t;
        t = spx[ii]; const float cx = hi ? t.y : t.x;
        t = spy[ii]; const float cy = hi ? t.y : t.x;
        t = spz[ii]; const float cz = hi ? t.y : t.x;
        const ull ncx = bc2(-cx), ncy = bc2(-cy), ncz = bc2(-cz);

        int cnt = 0;
        for (int basej = 0; basej < 2048; basej += 32) {
            const int j = basej + lane;
            ull s = sqdist2(px[j], py[j], pz[j], ncx, ncy, ncz);
            float d0, d1; unpack2(s, d0, d1);
            bool in0 = (d0 <= R2F);
            unsigned m0 = __ballot_sync(0xffffffffu, in0);
            if (in0) {
                int off = cnt + __popc(m0 & lanelt);
                if (off < BCAP)
                    buf[off] = (((ull)__float_as_uint(d0)) << 32) | (unsigned)j;
            }
            cnt += __popc(m0);
            bool in1 = (d1 <= R2F);
            unsigned m1 = __ballot_sync(0xffffffffu, in1);
            if (in1) {
                int off = cnt + __popc(m1 & lanelt);
                if (off < BCAP)
                    buf[off] = (((ull)__float_as_uint(d1)) << 32) | (unsigned)(j + 2048);
            }
            cnt += __popc(m1);
        }
        int ccnt = min(cnt, BCAP);
        __syncwarp();
        if (ccnt > KNB) {
            int n = KNB;
            while (n < ccnt) n <<= 1;          // n <= 512
            for (int i = ccnt + lane; i < n; i += 32) buf[i] = 0xffffffffffffffffull;
            __syncwarp();
            for (int k2 = 2; k2 <= n; k2 <<= 1) {
                for (int j2 = k2 >> 1; j2 > 0; j2 >>= 1) {
                    for (int i = lane; i < n; i += 32) {
                        int ixj = i ^ j2;
                        if (ixj > i) {
                            ull a = buf[i], q = buf[ixj];
                            bool up = ((i & k2) == 0);
                            if ((a > q) == up) { buf[i] = q; buf[ixj] = a; }
                        }
                    }
                    __syncwarp();
                }
            }
        }
        int nv = min(ccnt, KNB);
        for (int s2 = lane; s2 < KNB; s2 += 32) {
            int outi = (s2 < nv) ? (int)(buf[s2] & 0xffffffffull) : -1;
            g_nbr[((size_t)(b * MM + c)) * KNB + s2] = outi;
        }
        __syncwarp();
    }
}

// ---------------- Kernel C: t = x @ W1[0:32,:] (no bias) ----------------
__global__ void feat_kernel(const float* __restrict__ x, const float* __restrict__ W1) {
    __shared__ float Ws[CIN * 64];
    const int tid = threadIdx.x;
    for (int i = tid; i < CIN * 64; i += 256) Ws[i] = W1[i];
    __syncthreads();

    int g = blockIdx.x * 256 + tid;
    int p = g >> 2;
    int q = g & 3;

    float xr[32];
    const float4* xp = reinterpret_cast<const float4*>(x + (size_t)p * CIN);
#pragma unroll
    for (int k = 0; k < 8; ++k) {
        float4 v = xp[k];
        xr[4 * k + 0] = v.x; xr[4 * k + 1] = v.y; xr[4 * k + 2] = v.z; xr[4 * k + 3] = v.w;
    }
    float acc[16];
#pragma unroll
    for (int o = 0; o < 16; ++o) acc[o] = 0.0f;
#pragma unroll
    for (int i = 0; i < 32; ++i) {
        float xv = xr[i];
        const float4* wrow = reinterpret_cast<const float4*>(Ws + i * 64 + q * 16);
#pragma unroll
        for (int o4 = 0; o4 < 4; ++o4) {
            float4 w = wrow[o4];
            acc[o4 * 4 + 0] += xv * w.x;
            acc[o4 * 4 + 1] += xv * w.y;
            acc[o4 * 4 + 2] += xv * w.z;
            acc[o4 * 4 + 3] += xv * w.w;
        }
    }
    float4* tp = reinterpret_cast<float4*>(g_t + (size_t)p * 64 + q * 16);
#pragma unroll
    for (int o4 = 0; o4 < 4; ++o4)
        tp[o4] = make_float4(acc[o4 * 4 + 0], acc[o4 * 4 + 1], acc[o4 * 4 + 2], acc[o4 * 4 + 3]);
}

// ---------------- Kernel D: fused MLP + masked max-aggregate ----------------
#define SM_W3   4096
#define SM_W1P  12288
#define SM_B1   12480
#define SM_B2   12544
#define SM_B3   12608
#define SM_RED  12736
#define SM_TOT  13760

__global__ void __launch_bounds__(256) conv_kernel(
    const float* __restrict__ pos,
    const float* __restrict__ W1, const float* __restrict__ b1,
    const float* __restrict__ W2, const float* __restrict__ b2,
    const float* __restrict__ W3, const float* __restrict__ b3,
    float* __restrict__ out, int out_size)
{
    extern __shared__ float sm[];
    const int tid = threadIdx.x;

    for (int i = tid; i < 4096; i += 256) sm[i] = W2[i];
    for (int i = tid; i < 8192; i += 256) sm[SM_W3 + i] = W3[i];
    if (tid < 192) sm[SM_W1P + tid] = W1[CIN * 64 + tid];
    if (tid < 64)  sm[SM_B1 + tid] = b1[tid];
    if (tid < 64)  sm[SM_B2 + tid] = b2[tid];
    if (tid < 128) sm[SM_B3 + tid] = b3[tid];
    __syncthreads();

    const int group = tid >> 6;
    const int gtid = tid & 63;
    const int lane = tid & 31;
    const int wgrp = (tid >> 5) & 1;
    const int cid = blockIdx.x * 4 + group;
    const int b = cid >> 10;

    const int gi = g_fps[cid];
    const float* pb = pos + (size_t)b * NN * 3;
    const float cx = pb[gi * 3 + 0], cy = pb[gi * 3 + 1], cz = pb[gi * 3 + 2];

    const int nj = g_nbr[(size_t)cid * KNB + gtid];
    const bool valid = (nj >= 0);
    const int jj = valid ? nj : gi;
    const float rx = pb[jj * 3 + 0] - cx;
    const float ry = pb[jj * 3 + 1] - cy;
    const float rz = pb[jj * 3 + 2] - cz;

    // ---- layer 1 ----
    float h[64];
    const float4* tp = reinterpret_cast<const float4*>(g_t + ((size_t)b * NN + jj) * 64);
#pragma unroll
    for (int o4 = 0; o4 < 16; ++o4) {
        float4 tv = tp[o4];
        float4 bb = reinterpret_cast<const float4*>(sm + SM_B1)[o4];
        float4 w0 = reinterpret_cast<const float4*>(sm + SM_W1P)[o4];
        float4 w1 = reinterpret_cast<const float4*>(sm + SM_W1P + 64)[o4];
        float4 w2r = reinterpret_cast<const float4*>(sm + SM_W1P + 128)[o4];
        h[4 * o4 + 0] = fmaxf(tv.x + bb.x + rx * w0.x + ry * w1.x + rz * w2r.x, 0.0f);
        h[4 * o4 + 1] = fmaxf(tv.y + bb.y + rx * w0.y + ry * w1.y + rz * w2r.y, 0.0f);
        h[4 * o4 + 2] = fmaxf(tv.z + bb.z + rx * w0.z + ry * w1.z + rz * w2r.z, 0.0f);
        h[4 * o4 + 3] = fmaxf(tv.w + bb.w + rx * w0.w + ry * w1.w + rz * w2r.w, 0.0f);
    }

    // ---- layer 2 ----
    {
        ull acc2[32];
#pragma unroll
        for (int q = 0; q < 32; ++q)
            acc2[q] = pack2(sm[SM_B2 + 2 * q], sm[SM_B2 + 2 * q + 1]);
#pragma unroll
        for (int i = 0; i < 64; ++i) {
            ull hv = bc2(h[i]);
            const ulonglong2* wr = reinterpret_cast<const ulonglong2*>(sm + i * 64);
#pragma unroll
            for (int q = 0; q < 16; ++q) {
                ulonglong2 w = wr[q];
                fma2(acc2[2 * q + 0], hv, w.x);
                fma2(acc2[2 * q + 1], hv, w.y);
            }
        }
#pragma unroll
        for (int q = 0; q < 32; ++q) {
            float lo, hi;
            unpack2(acc2[q], lo, hi);
            h[2 * q + 0] = fmaxf(lo, 0.0f);
            h[2 * q + 1] = fmaxf(hi, 0.0f);
        }
    }

    // ---- layer 3 + masked max reduce ----
    for (int tile = 0; tile < 4; ++tile) {
        ull a3[16];
#pragma unroll
        for (int q = 0; q < 16; ++q)
            a3[q] = pack2(sm[SM_B3 + tile * 32 + 2 * q], sm[SM_B3 + tile * 32 + 2 * q + 1]);
#pragma unroll
        for (int i = 0; i < 64; ++i) {
            ull hv = bc2(h[i]);
            const ulonglong2* wr = reinterpret_cast<const ulonglong2*>(sm + SM_W3 + i * 128 + tile * 32);
#pragma unroll
            for (int q = 0; q < 8; ++q) {
                ulonglong2 w = wr[q];
                fma2(a3[2 * q + 0], hv, w.x);
                fma2(a3[2 * q + 1], hv, w.y);
            }
        }
        float v[32];
#pragma unroll
        for (int q = 0; q < 16; ++q) {
            float lo, hi;
            unpack2(a3[q], lo, hi);
            v[2 * q + 0] = valid ? lo : NEGV;
            v[2 * q + 1] = valid ? hi : NEGV;
        }
#pragma unroll
        for (int s = 16; s; s >>= 1) {
#pragma unroll
            for (int c = 0; c < 32; ++c)
                v[c] = fmaxf(v[c], __shfl_xor_sync(0xffffffffu, v[c], s));
        }
        float* red = sm + SM_RED + ((group * 4 + tile) * 2 + wgrp) * 32;
        if (lane == 0) {
#pragma unroll
            for (int q = 0; q < 8; ++q)
                reinterpret_cast<float4*>(red)[q] =
                    make_float4(v[4 * q + 0], v[4 * q + 1], v[4 * q + 2], v[4 * q + 3]);
        }
        __syncthreads();
        if (wgrp == 0) {
            const float* redA = sm + SM_RED + ((group * 4 + tile) * 2) * 32;
            float a = redA[lane];
            float bq = redA[32 + lane];
            int off = cid * 128 + tile * 32 + lane;
            if (off < out_size) out[off] = fmaxf(a, bq);
        }
    }
}

// ---------------- Kernel E: pos_out + batch_out tails ----------------
__global__ void tail_kernel(const float* __restrict__ pos, float* __restrict__ out, int out_size) {
    int i = blockIdx.x * 256 + threadIdx.x;
    if (i >= BB * MM) return;
    int b = i >> 10;
    int gi = g_fps[i];
    const float* pb = pos + (size_t)b * NN * 3;
    const int OX = BB * MM * 128;
    const int OP = OX + BB * MM * 3;
    const int OT = OP + BB * MM;
    if (out_size >= OP) {
        out[OX + i * 3 + 0] = pb[gi * 3 + 0];
        out[OX + i * 3 + 1] = pb[gi * 3 + 1];
        out[OX + i * 3 + 2] = pb[gi * 3 + 2];
    }
    if (out_size >= OT) out[OP + i] = (float)b;
}

extern "C" void kernel_launch(void* const* d_in, const int* in_sizes, int n_in,
                              void* d_out, int out_size) {
    const float* x   = (const float*)d_in[0];
    const float* pos = (const float*)d_in[1];
    const float* W1  = (const float*)d_in[3];
    const float* b1  = (const float*)d_in[4];
    const float* W2  = (const float*)d_in[5];
    const float* b2  = (const float*)d_in[6];
    const float* W3  = (const float*)d_in[7];
    const float* b3  = (const float*)d_in[8];
    float* out = (float*)d_out;

    const int smA = 3 * NN * 4;                        // 49152
    const int smB = 3 * NN * 4 + 8 * BCAP * 8;         // 81920
    const int smD = SM_TOT * 4;                        // 55040

    cudaFuncSetAttribute(fps_kernel,   cudaFuncAttributeMaxDynamicSharedMemorySize, smA);
    cudaFuncSetAttribute(ballq_kernel, cudaFuncAttributeMaxDynamicSharedMemorySize, smB);
    cudaFuncSetAttribute(conv_kernel,  cudaFuncAttributeMaxDynamicSharedMemorySize, smD);
    // carveout: let 2 (ballq) / 4 (conv) blocks co-reside per SM instead of 1
    cudaFuncSetAttribute(fps_kernel,   cudaFuncAttributePreferredSharedMemoryCarveout, 100);
    cudaFuncSetAttribute(ballq_kernel, cudaFuncAttributePreferredSharedMemoryCarveout, 100);
    cudaFuncSetAttribute(conv_kernel,  cudaFuncAttributePreferredSharedMemoryCarveout, 100);

    fps_kernel<<<BB, 512, smA>>>(pos);
    ballq_kernel<<<dim3(64, BB), 256, smB>>>(pos);
    feat_kernel<<<(BB * NN * 4) / 256, 256>>>(x, W1);
    conv_kernel<<<(BB * MM) / 4, 256, smD>>>(pos, W1, b1, W2, b2, W3, b3, out, out_size);
    tail_kernel<<<(BB * MM) / 256, 256>>>(pos, out, out_size);
}

// round 8
// speedup vs baseline: 1.5978x; 1.2029x over previous
#include <cuda_runtime.h>
#include <cuda_bf16.h>
#include <cstdint>

// Problem constants
#define BB   8
#define NN   4096
#define MM   1024
#define CIN  32
#define KNB  64
#define NEGV (-1e10f)
#define R2F  (0.04f)

// Scratch (device globals: allocation-free)
__device__ int   g_fps[BB * MM];
__device__ float g_t[(size_t)BB * NN * 64];
__device__ int   g_nbr[(size_t)BB * MM * KNB];

typedef unsigned long long ull;

// ---------------- helpers: packed f32x2 ----------------
__device__ __forceinline__ ull pack2(float lo, float hi) {
    ull r; asm("mov.b64 %0, {%1, %2};" : "=l"(r) : "f"(lo), "f"(hi)); return r;
}
__device__ __forceinline__ ull bc2(float v) {
    ull r; asm("mov.b64 %0, {%1, %1};" : "=l"(r) : "f"(v)); return r;
}
__device__ __forceinline__ void unpack2(ull v, float& lo, float& hi) {
    asm("mov.b64 {%0, %1}, %2;" : "=f"(lo), "=f"(hi) : "l"(v));
}
__device__ __forceinline__ void fma2(ull& acc, ull a, ull b) {
    asm("fma.rn.f32x2 %0, %1, %2, %0;" : "+l"(acc) : "l"(a), "l"(b));
}
__device__ __forceinline__ ull add2(ull a, ull b) {
    ull r; asm("add.rn.f32x2 %0, %1, %2;" : "=l"(r) : "l"(a), "l"(b)); return r;
}
__device__ __forceinline__ ull mul2(ull a, ull b) {
    ull r; asm("mul.rn.f32x2 %0, %1, %2;" : "=l"(r) : "l"(a), "l"(b)); return r;
}
// packed sqdist of 2 points vs broadcast negated center: per-component identical
// to __fadd_rn(__fadd_rn(__fmul_rn(dx,dx),__fmul_rn(dy,dy)),__fmul_rn(dz,dz))
__device__ __forceinline__ ull sqdist2(ull X, ull Y, ull Z, ull ncx, ull ncy, ull ncz) {
    ull dx = add2(X, ncx), dy = add2(Y, ncy), dz = add2(Z, ncz);
    return add2(add2(mul2(dx, dx), mul2(dy, dy)), mul2(dz, dz));
}
__device__ __forceinline__ ull umax64(ull a, ull b) { return a > b ? a : b; }

__device__ __forceinline__ float sqdist(float ax, float ay, float az,
                                        float bx, float by, float bz) {
    float dx = ax - bx, dy = ay - by, dz = az - bz;
    return __fadd_rn(__fadd_rn(__fmul_rn(dx, dx), __fmul_rn(dy, dy)), __fmul_rn(dz, dz));
}

// ---------------- Kernel A: farthest point sampling (v3) ----------------
// one block per batch, 256 threads, 16 points/thread in registers.
// Single __syncthreads per iteration: u64 argmax keys, parity double-buffer.
__global__ void __launch_bounds__(256) fps_kernel(const float* __restrict__ pos) {
    extern __shared__ float sm[];
    float* sx = sm;
    float* sy = sm + NN;
    float* sz = sm + 2 * NN;
    __shared__ alignas(16) ull skey[2][8];

    const int b = blockIdx.x;
    const int tid = threadIdx.x;
    const float* pb = pos + (size_t)b * NN * 3;

    for (int i = tid; i < NN; i += 256) {
        sx[i] = pb[i * 3 + 0];
        sy[i] = pb[i * 3 + 1];
        sz[i] = pb[i * 3 + 2];
    }
    if (tid == 0) g_fps[b * MM] = 0;
    __syncthreads();

    const int base = tid * 16;
    ull X[8], Y[8], Z[8];
#pragma unroll
    for (int j = 0; j < 8; ++j) {
        X[j] = pack2(sx[base + 2 * j], sx[base + 2 * j + 1]);
        Y[j] = pack2(sy[base + 2 * j], sy[base + 2 * j + 1]);
        Z[j] = pack2(sz[base + 2 * j], sz[base + 2 * j + 1]);
    }
    float dmin[16];
#pragma unroll
    for (int j = 0; j < 16; ++j) dmin[j] = 1e10f;

    int last = 0;
    for (int it = 1; it < MM; ++it) {
        const float lx = sx[last], ly = sy[last], lz = sz[last];
        const ull nlx = bc2(-lx), nly = bc2(-ly), nlz = bc2(-lz);
        float bv = -1.0f; int bi = 0;
#pragma unroll
        for (int j = 0; j < 8; ++j) {
            ull s = sqdist2(X[j], Y[j], Z[j], nlx, nly, nlz);
            float d0, d1; unpack2(s, d0, d1);
            float m0 = fminf(dmin[2 * j + 0], d0); dmin[2 * j + 0] = m0;
            float m1 = fminf(dmin[2 * j + 1], d1); dmin[2 * j + 1] = m1;
            if (m0 > bv) { bv = m0; bi = base + 2 * j; }     // strict > keeps lowest idx
            if (m1 > bv) { bv = m1; bi = base + 2 * j + 1; }
        }
        // key: higher dmin wins; tie -> larger (4095-idx) -> smaller idx wins
        ull key = (((ull)__float_as_uint(bv)) << 32) | (unsigned)(4095 - bi);
#pragma unroll
        for (int off = 16; off; off >>= 1) {
            ull o = __shfl_down_sync(0xffffffffu, key, off);
            key = umax64(key, o);
        }
        const int p = it & 1;
        if ((tid & 31) == 0) skey[p][tid >> 5] = key;
        __syncthreads();
        const ulonglong2* sk = reinterpret_cast<const ulonglong2*>(skey[p]);
        ulonglong2 a = sk[0], c = sk[1], d = sk[2], e = sk[3];
        ull m = umax64(umax64(umax64(a.x, a.y), umax64(c.x, c.y)),
                       umax64(umax64(d.x, d.y), umax64(e.x, e.y)));
        last = 4095 - (int)(m & 0xFFFFull);
        if (tid == 0) g_fps[b * MM + it] = last;
        // no 2nd barrier: next iter writes skey[p^1]; a warp can only write
        // skey[p] again after the it+1 barrier, past which all reads of skey[p]
        // (which occur before that barrier) have completed.
    }
}

// ---------------- Kernel B: ball query + exact 64-NN selection ----------------
// grid (64 chunks, 8 batches), 256 threads (8 warps), warp handles 2 centroids
#define BCAP 512
__global__ void ballq_kernel(const float* __restrict__ pos) {
    extern __shared__ float sm[];
    float2* spx = (float2*)sm;                 // 2048
    float2* spy = spx + 2048;
    float2* spz = spy + 2048;
    ull* bufAll = (ull*)(spz + 2048);          // 8 warps * 512

    const int b = blockIdx.y;
    const int chunk = blockIdx.x;              // 0..63
    const int tid = threadIdx.x;
    const int warpId = tid >> 5;
    const int lane = tid & 31;
    const unsigned lanelt = (1u << lane) - 1u;
    const float* pb = pos + (size_t)b * NN * 3;

    for (int k = tid; k < NN * 3; k += 256) {
        float f = pb[k];
        int i = k / 3, comp = k - 3 * i;
        float* dst = (comp == 0) ? (float*)spx : (comp == 1) ? (float*)spy : (float*)spz;
        dst[(i & 2047) * 2 + (i >> 11)] = f;
    }
    __syncthreads();

    const ull* px = (const ull*)spx;
    const ull* py = (const ull*)spy;
    const ull* pz = (const ull*)spz;
    ull* buf = bufAll + (size_t)warpId * BCAP;

    for (int cc = 0; cc < 2; ++cc) {
        const int c = chunk * 16 + warpId * 2 + cc;
        const int gi = g_fps[b * MM + c];
        const int hi = gi >> 11, ii = gi & 2047;
        float2 t;
        t = spx[ii]; const float cx = hi ? t.y : t.x;
        t = spy[ii]; const float cy = hi ? t.y : t.x;
        t = spz[ii]; const float cz = hi ? t.y : t.x;
        const ull ncx = bc2(-cx), ncy = bc2(-cy), ncz = bc2(-cz);

        int cnt = 0;
        for (int basej = 0; basej < 2048; basej += 32) {
            const int j = basej + lane;
            ull s = sqdist2(px[j], py[j], pz[j], ncx, ncy, ncz);
            float d0, d1; unpack2(s, d0, d1);
            bool in0 = (d0 <= R2F);
            unsigned m0 = __ballot_sync(0xffffffffu, in0);
            if (in0) {
                int off = cnt + __popc(m0 & lanelt);
                if (off < BCAP)
                    buf[off] = (((ull)__float_as_uint(d0)) << 32) | (unsigned)j;
            }
            cnt += __popc(m0);
            bool in1 = (d1 <= R2F);
            unsigned m1 = __ballot_sync(0xffffffffu, in1);
            if (in1) {
                int off = cnt + __popc(m1 & lanelt);
                if (off < BCAP)
                    buf[off] = (((ull)__float_as_uint(d1)) << 32) | (unsigned)(j + 2048);
            }
            cnt += __popc(m1);
        }
        int ccnt = min(cnt, BCAP);
        __syncwarp();
        if (ccnt > KNB) {
            int n = KNB;
            while (n < ccnt) n <<= 1;          // n <= 512
            for (int i = ccnt + lane; i < n; i += 32) buf[i] = 0xffffffffffffffffull;
            __syncwarp();
            for (int k2 = 2; k2 <= n; k2 <<= 1) {
                for (int j2 = k2 >> 1; j2 > 0; j2 >>= 1) {
                    for (int i = lane; i < n; i += 32) {
                        int ixj = i ^ j2;
                        if (ixj > i) {
                            ull a = buf[i], q = buf[ixj];
                            bool up = ((i & k2) == 0);
                            if ((a > q) == up) { buf[i] = q; buf[ixj] = a; }
                        }
                    }
                    __syncwarp();
                }
            }
        }
        int nv = min(ccnt, KNB);
        for (int s2 = lane; s2 < KNB; s2 += 32) {
            int outi = (s2 < nv) ? (int)(buf[s2] & 0xffffffffull) : -1;
            g_nbr[((size_t)(b * MM + c)) * KNB + s2] = outi;
        }
        __syncwarp();
    }
}

// ---------------- Kernel C: t = x @ W1[0:32,:] (no bias) ----------------
__global__ void feat_kernel(const float* __restrict__ x, const float* __restrict__ W1) {
    __shared__ float Ws[CIN * 64];
    const int tid = threadIdx.x;
    for (int i = tid; i < CIN * 64; i += 256) Ws[i] = W1[i];
    __syncthreads();

    int g = blockIdx.x * 256 + tid;
    int p = g >> 2;
    int q = g & 3;

    float xr[32];
    const float4* xp = reinterpret_cast<const float4*>(x + (size_t)p * CIN);
#pragma unroll
    for (int k = 0; k < 8; ++k) {
        float4 v = xp[k];
        xr[4 * k + 0] = v.x; xr[4 * k + 1] = v.y; xr[4 * k + 2] = v.z; xr[4 * k + 3] = v.w;
    }
    float acc[16];
#pragma unroll
    for (int o = 0; o < 16; ++o) acc[o] = 0.0f;
#pragma unroll
    for (int i = 0; i < 32; ++i) {
        float xv = xr[i];
        const float4* wrow = reinterpret_cast<const float4*>(Ws + i * 64 + q * 16);
#pragma unroll
        for (int o4 = 0; o4 < 4; ++o4) {
            float4 w = wrow[o4];
            acc[o4 * 4 + 0] += xv * w.x;
            acc[o4 * 4 + 1] += xv * w.y;
            acc[o4 * 4 + 2] += xv * w.z;
            acc[o4 * 4 + 3] += xv * w.w;
        }
    }
    float4* tp = reinterpret_cast<float4*>(g_t + (size_t)p * 64 + q * 16);
#pragma unroll
    for (int o4 = 0; o4 < 4; ++o4)
        tp[o4] = make_float4(acc[o4 * 4 + 0], acc[o4 * 4 + 1], acc[o4 * 4 + 2], acc[o4 * 4 + 3]);
}

// ---------------- Kernel D: fused MLP + masked max-aggregate (v2) ----------------
// 256 threads = 4 groups of 64; launch_bounds(256,2) => <=128 regs, 2 blocks/SM.
// Layer 2 split into two 32-output halves; half-0 activations parked in smem.
#define SM_W3   4096
#define SM_W1P  12288
#define SM_B1   12480
#define SM_B2   12544
#define SM_B3   12608
#define SM_RED  12736
#define SM_H2   13760
#define SM_TOT2 21952   /* floats: 13760 + 8192 */

__global__ void __launch_bounds__(256, 2) conv_kernel(
    const float* __restrict__ pos,
    const float* __restrict__ W1, const float* __restrict__ b1,
    const float* __restrict__ W2, const float* __restrict__ b2,
    const float* __restrict__ W3, const float* __restrict__ b3,
    float* __restrict__ out, int out_size)
{
    extern __shared__ float sm[];
    const int tid = threadIdx.x;

    for (int i = tid; i < 4096; i += 256) sm[i] = W2[i];
    for (int i = tid; i < 8192; i += 256) sm[SM_W3 + i] = W3[i];
    if (tid < 192) sm[SM_W1P + tid] = W1[CIN * 64 + tid];
    if (tid < 64)  sm[SM_B1 + tid] = b1[tid];
    if (tid < 64)  sm[SM_B2 + tid] = b2[tid];
    if (tid < 128) sm[SM_B3 + tid] = b3[tid];
    __syncthreads();

    const int group = tid >> 6;
    const int gtid = tid & 63;
    const int lane = tid & 31;
    const int wgrp = (tid >> 5) & 1;
    const int cid = blockIdx.x * 4 + group;
    const int b = cid >> 10;

    const int gi = g_fps[cid];
    const float* pb = pos + (size_t)b * NN * 3;
    const float cx = pb[gi * 3 + 0], cy = pb[gi * 3 + 1], cz = pb[gi * 3 + 2];

    const int nj = g_nbr[(size_t)cid * KNB + gtid];
    const bool valid = (nj >= 0);
    const int jj = valid ? nj : gi;
    const float rx = pb[jj * 3 + 0] - cx;
    const float ry = pb[jj * 3 + 1] - cy;
    const float rz = pb[jj * 3 + 2] - cz;

    // ---- layer 1: h = relu(t + b1 + rel @ W1p) ----
    float h[64];
    const float4* tp = reinterpret_cast<const float4*>(g_t + ((size_t)b * NN + jj) * 64);
#pragma unroll
    for (int o4 = 0; o4 < 16; ++o4) {
        float4 tv = tp[o4];
        float4 bb = reinterpret_cast<const float4*>(sm + SM_B1)[o4];
        float4 w0 = reinterpret_cast<const float4*>(sm + SM_W1P)[o4];
        float4 w1 = reinterpret_cast<const float4*>(sm + SM_W1P + 64)[o4];
        float4 w2r = reinterpret_cast<const float4*>(sm + SM_W1P + 128)[o4];
        h[4 * o4 + 0] = fmaxf(tv.x + bb.x + rx * w0.x + ry * w1.x + rz * w2r.x, 0.0f);
        h[4 * o4 + 1] = fmaxf(tv.y + bb.y + rx * w0.y + ry * w1.y + rz * w2r.y, 0.0f);
        h[4 * o4 + 2] = fmaxf(tv.z + bb.z + rx * w0.z + ry * w1.z + rz * w2r.z, 0.0f);
        h[4 * o4 + 3] = fmaxf(tv.w + bb.w + rx * w0.w + ry * w1.w + rz * w2r.w, 0.0f);
    }

    // ---- layer 2 half 0: outputs [0,32) -> smem H2[c*256+tid] ----
    {
        ull acc[16];
#pragma unroll
        for (int q = 0; q < 16; ++q)
            acc[q] = pack2(sm[SM_B2 + 2 * q], sm[SM_B2 + 2 * q + 1]);
#pragma unroll
        for (int i = 0; i < 64; ++i) {
            ull hv = bc2(h[i]);
            const ulonglong2* wr = reinterpret_cast<const ulonglong2*>(sm + i * 64);
#pragma unroll
            for (int q = 0; q < 8; ++q) {
                ulonglong2 w = wr[q];
                fma2(acc[2 * q + 0], hv, w.x);
                fma2(acc[2 * q + 1], hv, w.y);
            }
        }
#pragma unroll
        for (int q = 0; q < 16; ++q) {
            float lo, hi;
            unpack2(acc[q], lo, hi);
            sm[SM_H2 + (2 * q + 0) * 256 + tid] = fmaxf(lo, 0.0f);
            sm[SM_H2 + (2 * q + 1) * 256 + tid] = fmaxf(hi, 0.0f);
        }
    }
    // ---- layer 2 half 1: outputs [32,64) -> h[32..63], then reload h[0..31] ----
    {
        ull acc[16];
#pragma unroll
        for (int q = 0; q < 16; ++q)
            acc[q] = pack2(sm[SM_B2 + 32 + 2 * q], sm[SM_B2 + 32 + 2 * q + 1]);
#pragma unroll
        for (int i = 0; i < 64; ++i) {
            ull hv = bc2(h[i]);
            const ulonglong2* wr = reinterpret_cast<const ulonglong2*>(sm + i * 64 + 32);
#pragma unroll
            for (int q = 0; q < 8; ++q) {
                ulonglong2 w = wr[q];
                fma2(acc[2 * q + 0], hv, w.x);
                fma2(acc[2 * q + 1], hv, w.y);
            }
        }
#pragma unroll
        for (int q = 0; q < 16; ++q) {
            float lo, hi;
            unpack2(acc[q], lo, hi);
            h[32 + 2 * q + 0] = fmaxf(lo, 0.0f);
            h[32 + 2 * q + 1] = fmaxf(hi, 0.0f);
        }
#pragma unroll
        for (int c = 0; c < 32; ++c)
            h[c] = sm[SM_H2 + c * 256 + tid];
    }

    // ---- layer 3 (4 tiles of 32 out) + masked max reduce ----
    for (int tile = 0; tile < 4; ++tile) {
        ull a3[16];
#pragma unroll
        for (int q = 0; q < 16; ++q)
            a3[q] = pack2(sm[SM_B3 + tile * 32 + 2 * q], sm[SM_B3 + tile * 32 + 2 * q + 1]);
#pragma unroll
        for (int i = 0; i < 64; ++i) {
            ull hv = bc2(h[i]);
            const ulonglong2* wr = reinterpret_cast<const ulonglong2*>(sm + SM_W3 + i * 128 + tile * 32);
#pragma unroll
            for (int q = 0; q < 8; ++q) {
                ulonglong2 w = wr[q];
                fma2(a3[2 * q + 0], hv, w.x);
                fma2(a3[2 * q + 1], hv, w.y);
            }
        }
        float v[32];
#pragma unroll
        for (int q = 0; q < 16; ++q) {
            float lo, hi;
            unpack2(a3[q], lo, hi);
            v[2 * q + 0] = valid ? lo : NEGV;
            v[2 * q + 1] = valid ? hi : NEGV;
        }
#pragma unroll
        for (int s = 16; s; s >>= 1) {
#pragma unroll
            for (int c = 0; c < 32; ++c)
                v[c] = fmaxf(v[c], __shfl_xor_sync(0xffffffffu, v[c], s));
        }
        float* red = sm + SM_RED + ((group * 4 + tile) * 2 + wgrp) * 32;
        if (lane == 0) {
#pragma unroll
            for (int q = 0; q < 8; ++q)
                reinterpret_cast<float4*>(red)[q] =
                    make_float4(v[4 * q + 0], v[4 * q + 1], v[4 * q + 2], v[4 * q + 3]);
        }
        __syncthreads();
        if (wgrp == 0) {
            const float* redA = sm + SM_RED + ((group * 4 + tile) * 2) * 32;
            float a = redA[lane];
            float bq = redA[32 + lane];
            int off = cid * 128 + tile * 32 + lane;
            if (off < out_size) out[off] = fmaxf(a, bq);
        }
    }
}

// ---------------- Kernel E: pos_out + batch_out tails ----------------
__global__ void tail_kernel(const float* __restrict__ pos, float* __restrict__ out, int out_size) {
    int i = blockIdx.x * 256 + threadIdx.x;
    if (i >= BB * MM) return;
    int b = i >> 10;
    int gi = g_fps[i];
    const float* pb = pos + (size_t)b * NN * 3;
    const int OX = BB * MM * 128;
    const int OP = OX + BB * MM * 3;
    const int OT = OP + BB * MM;
    if (out_size >= OP) {
        out[OX + i * 3 + 0] = pb[gi * 3 + 0];
        out[OX + i * 3 + 1] = pb[gi * 3 + 1];
        out[OX + i * 3 + 2] = pb[gi * 3 + 2];
    }
    if (out_size >= OT) out[OP + i] = (float)b;
}

extern "C" void kernel_launch(void* const* d_in, const int* in_sizes, int n_in,
                              void* d_out, int out_size) {
    const float* x   = (const float*)d_in[0];
    const float* pos = (const float*)d_in[1];
    const float* W1  = (const float*)d_in[3];
    const float* b1  = (const float*)d_in[4];
    const float* W2  = (const float*)d_in[5];
    const float* b2  = (const float*)d_in[6];
    const float* W3  = (const float*)d_in[7];
    const float* b3  = (const float*)d_in[8];
    float* out = (float*)d_out;

    const int smA = 3 * NN * 4;                        // 49152
    const int smB = 3 * NN * 4 + 8 * BCAP * 8;         // 81920
    const int smD = SM_TOT2 * 4;                       // 87808

    cudaFuncSetAttribute(fps_kernel,   cudaFuncAttributeMaxDynamicSharedMemorySize, smA);
    cudaFuncSetAttribute(ballq_kernel, cudaFuncAttributeMaxDynamicSharedMemorySize, smB);
    cudaFuncSetAttribute(conv_kernel,  cudaFuncAttributeMaxDynamicSharedMemorySize, smD);
    cudaFuncSetAttribute(fps_kernel,   cudaFuncAttributePreferredSharedMemoryCarveout, 100);
    cudaFuncSetAttribute(ballq_kernel, cudaFuncAttributePreferredSharedMemoryCarveout, 100);
    cudaFuncSetAttribute(conv_kernel,  cudaFuncAttributePreferredSharedMemoryCarveout, 100);

    fps_kernel<<<BB, 256, smA>>>(pos);
    ballq_kernel<<<dim3(64, BB), 256, smB>>>(pos);
    feat_kernel<<<(BB * NN * 4) / 256, 256>>>(x, W1);
    conv_kernel<<<(BB * MM) / 4, 256, smD>>>(pos, W1, b1, W2, b2, W3, b3, out, out_size);
    tail_kernel<<<(BB * MM) / 256, 256>>>(pos, out, out_size);
}